// round 4
// baseline (speedup 1.0000x reference)
#include <cuda_runtime.h>
#include <cuda_bf16.h>
#include <cstdint>

typedef __nv_bfloat16 bf16;

#define BATCH 2
#define TQ    2048
#define HID   1280
#define NH    20
#define HD    64
#define CROSSD 2048
#define SENC  77
#define SPAD  128
#define FFD   5120
#define M1    (BATCH*TQ)     /* 4096 */
#define MENC  (BATCH*SENC)   /* 154  */
#define NBH   (BATCH*NH)     /* 40   */

// ---------------- scratch (device globals; no allocation) ----------------
__device__ float g_h   [M1*HID];
__device__ float g_p1  [M1*HID];
__device__ float g_p2  [M1*HID];
__device__ float g_p3  [M1*HID];
__device__ float g_qh  [(size_t)NBH*TQ*HD];
__device__ float g_kh  [(size_t)NBH*TQ*HD];
__device__ float g_vT  [(size_t)NBH*HD*TQ];
__device__ float g_scores[(size_t)NBH*TQ*TQ];   // 671 MB fp32 (softmax in-place)
__device__ float g_att [M1*HID];
__device__ float g_x   [M1*HID];
__device__ float g_proj[(size_t)M1*2*FFD];
__device__ float g_ff  [(size_t)M1*FFD];

// ---------------- elementwise kernels ----------------
__global__ void ln_kernel(const float* __restrict__ x, const float* __restrict__ g,
                          const float* __restrict__ b, float* __restrict__ out) {
    __shared__ float red[256];
    int row = blockIdx.x, tid = threadIdx.x;
    const float* xr = x + (long long)row * HID;
    float v[5], s = 0.f;
#pragma unroll
    for (int i = 0; i < 5; i++) { v[i] = xr[tid + i * 256]; s += v[i]; }
    red[tid] = s; __syncthreads();
    for (int o = 128; o > 0; o >>= 1) { if (tid < o) red[tid] += red[tid + o]; __syncthreads(); }
    float mu = red[0] * (1.0f / HID);
    __syncthreads();
    float sq = 0.f;
#pragma unroll
    for (int i = 0; i < 5; i++) { float d = v[i] - mu; sq += d * d; }
    red[tid] = sq; __syncthreads();
    for (int o = 128; o > 0; o >>= 1) { if (tid < o) red[tid] += red[tid + o]; __syncthreads(); }
    float rs = rsqrtf(red[0] * (1.0f / HID) + 1e-5f);
#pragma unroll
    for (int i = 0; i < 5; i++) {
        int c = tid + i * 256;
        out[(long long)row * HID + c] = (v[i] - mu) * rs * g[c] + b[c];
    }
}

// q proj rows [b*t][HID] -> [bh][t][d]
__global__ void reshape_q_kernel(const float* __restrict__ q, float* __restrict__ qh) {
    long long idx = (long long)blockIdx.x * blockDim.x + threadIdx.x;
    if (idx >= (long long)NBH * TQ * HD) return;
    int d = idx & (HD - 1);
    long long r = idx >> 6;
    int t = (int)(r % TQ);
    long long bh = r / TQ;
    int h = (int)(bh % NH), b = (int)(bh / NH);
    qh[idx] = q[((long long)(b * TQ + t)) * HID + h * HD + d];
}

// k proj rows [b*s][HID] -> [bh][s_pad][d] with zero pad
__global__ void reshape_k_kernel(const float* __restrict__ k, float* __restrict__ kh, int S, int Spad) {
    long long idx = (long long)blockIdx.x * blockDim.x + threadIdx.x;
    long long tot = (long long)NBH * Spad * HD;
    if (idx >= tot) return;
    int d = idx & (HD - 1);
    long long r = idx >> 6;
    int s = (int)(r % Spad);
    long long bh = r / Spad;
    int h = (int)(bh % NH), b = (int)(bh / NH);
    float val = 0.f;
    if (s < S) val = k[((long long)(b * S + s)) * HID + h * HD + d];
    kh[idx] = val;
}

// v proj rows [b*s][HID] -> vT [bh][d][s_pad] with zero pad
__global__ void reshape_vT_kernel(const float* __restrict__ v, float* __restrict__ vT, int S, int Spad) {
    long long idx = (long long)blockIdx.x * blockDim.x + threadIdx.x;
    long long tot = (long long)NBH * HD * Spad;
    if (idx >= tot) return;
    int s = (int)(idx % Spad);
    long long r = idx / Spad;
    int d = (int)(r % HD);
    long long bh = r / HD;
    int h = (int)(bh % NH), b = (int)(bh / NH);
    float val = 0.f;
    if (s < S) val = v[((long long)(b * S + s)) * HID + h * HD + d];
    vT[idx] = val;
}

// in-place softmax over rows of length Spad (valid cols = Sval)
__global__ void softmax_kernel(float* __restrict__ S, int Spad, int Sval) {
    __shared__ float red[256];
    long long row = blockIdx.x;
    float* sr = S + row * (long long)Spad;
    int tid = threadIdx.x;
    float vals[8];
    int cnt = 0;
    float mx = -1e30f;
    for (int j = tid; j < Sval; j += 256) { float v = sr[j]; vals[cnt++] = v; mx = fmaxf(mx, v); }
    red[tid] = mx; __syncthreads();
    for (int o = 128; o > 0; o >>= 1) { if (tid < o) red[tid] = fmaxf(red[tid], red[tid + o]); __syncthreads(); }
    mx = red[0]; __syncthreads();
    float sum = 0.f;
    for (int i = 0; i < cnt; i++) { vals[i] = expf(vals[i] - mx); sum += vals[i]; }
    red[tid] = sum; __syncthreads();
    for (int o = 128; o > 0; o >>= 1) { if (tid < o) red[tid] += red[tid + o]; __syncthreads(); }
    float inv = 1.f / red[0];
    cnt = 0;
    for (int j = tid; j < Spad; j += 256) {
        float o = (j < Sval) ? vals[cnt++] * inv : 0.f;
        sr[j] = o;
    }
}

__global__ void geglu_kernel(const float* __restrict__ proj, float* __restrict__ out) {
    long long i = (long long)blockIdx.x * blockDim.x + threadIdx.x;
    if (i >= (long long)M1 * FFD) return;
    long long r = i / FFD;
    int c = (int)(i % FFD);
    float x1 = proj[r * (2 * FFD) + c];
    float x2 = proj[r * (2 * FFD) + FFD + c];
    float gel = 0.5f * x2 * (1.0f + erff(x2 * 0.7071067811865476f));
    out[i] = x1 * gel;
}

// ---------------- generic batched split-bf16 tensor-core GEMM ----------------
// C[z][M][N] = scale * (A[z] @ W[z]^T) + bias + residual   (all fp32 in/out)
// Internally: A = Ah + Al, W = Wh + Wl (bf16 hi/lo split);
// product = Ah*Wh + Ah*Wl + Al*Wh accumulated in fp32 (~fp32 fidelity).
__device__ __forceinline__ void mma16816(float c[4], const uint32_t a[4], const uint32_t b[2]) {
    asm volatile(
        "mma.sync.aligned.m16n8k16.row.col.f32.bf16.bf16.f32 "
        "{%0,%1,%2,%3}, {%4,%5,%6,%7}, {%8,%9}, {%0,%1,%2,%3};\n"
        : "+f"(c[0]), "+f"(c[1]), "+f"(c[2]), "+f"(c[3])
        : "r"(a[0]), "r"(a[1]), "r"(a[2]), "r"(a[3]), "r"(b[0]), "r"(b[1]));
}

__global__ __launch_bounds__(256) void gemm_kernel(
    const float* __restrict__ A, const float* __restrict__ W,
    const float* __restrict__ bias, const float* __restrict__ residual,
    float* __restrict__ C,
    int M, int N, int K,
    long long aStride, long long wStride,
    long long cHi, long long cLo, int cDiv, int ldc, float scale)
{
    __shared__ __align__(16) bf16 Ah[128][40];
    __shared__ __align__(16) bf16 Al[128][40];
    __shared__ __align__(16) bf16 Bh[128][40];
    __shared__ __align__(16) bf16 Bl[128][40];

    int z = blockIdx.z;
    A += (long long)z * aStride;
    W += (long long)z * wStride;
    long long cOff = (long long)(z / cDiv) * cHi + (long long)(z % cDiv) * cLo;

    int tid = threadIdx.x;
    int lane = tid & 31, warp = tid >> 5;
    int wm = warp >> 1, wn = warp & 1;
    int rowBase = blockIdx.y * 128;
    int colBase = blockIdx.x * 128;

    float acc[2][8][4];
#pragma unroll
    for (int i = 0; i < 2; i++)
#pragma unroll
        for (int j = 0; j < 8; j++)
#pragma unroll
            for (int l = 0; l < 4; l++) acc[i][j][l] = 0.f;

    int kTiles = K >> 5;
    for (int kt = 0; kt < kTiles; ++kt) {
        int k0 = kt << 5;
        // load 128x32 fp32 tiles of A and W, split into hi/lo bf16 smem
#pragma unroll
        for (int it = 0; it < 4; ++it) {
            int i = tid + it * 256;         // 0..1023, each covers float4
            int r = i >> 3;
            int c = (i & 7) << 2;
            float4 va = make_float4(0.f, 0.f, 0.f, 0.f);
            int gr = rowBase + r;
            if (gr < M) va = *(const float4*)(A + (long long)gr * K + k0 + c);
            bf16 h0 = __float2bfloat16(va.x);
            bf16 h1 = __float2bfloat16(va.y);
            bf16 h2 = __float2bfloat16(va.z);
            bf16 h3 = __float2bfloat16(va.w);
            Ah[r][c+0] = h0; Ah[r][c+1] = h1; Ah[r][c+2] = h2; Ah[r][c+3] = h3;
            Al[r][c+0] = __float2bfloat16(va.x - __bfloat162float(h0));
            Al[r][c+1] = __float2bfloat16(va.y - __bfloat162float(h1));
            Al[r][c+2] = __float2bfloat16(va.z - __bfloat162float(h2));
            Al[r][c+3] = __float2bfloat16(va.w - __bfloat162float(h3));

            float4 vb = make_float4(0.f, 0.f, 0.f, 0.f);
            int gn = colBase + r;
            if (gn < N) vb = *(const float4*)(W + (long long)gn * K + k0 + c);
            bf16 g0 = __float2bfloat16(vb.x);
            bf16 g1 = __float2bfloat16(vb.y);
            bf16 g2 = __float2bfloat16(vb.z);
            bf16 g3 = __float2bfloat16(vb.w);
            Bh[r][c+0] = g0; Bh[r][c+1] = g1; Bh[r][c+2] = g2; Bh[r][c+3] = g3;
            Bl[r][c+0] = __float2bfloat16(vb.x - __bfloat162float(g0));
            Bl[r][c+1] = __float2bfloat16(vb.y - __bfloat162float(g1));
            Bl[r][c+2] = __float2bfloat16(vb.z - __bfloat162float(g2));
            Bl[r][c+3] = __float2bfloat16(vb.w - __bfloat162float(g3));
        }
        __syncthreads();
#pragma unroll
        for (int kk = 0; kk < 32; kk += 16) {
            uint32_t ah[2][4], al[2][4];
#pragma unroll
            for (int mt = 0; mt < 2; ++mt) {
                int r = wm * 32 + mt * 16 + (lane >> 2);
                int c = kk + (lane & 3) * 2;
                ah[mt][0] = *(const uint32_t*)(&Ah[r][c]);
                ah[mt][1] = *(const uint32_t*)(&Ah[r + 8][c]);
                ah[mt][2] = *(const uint32_t*)(&Ah[r][c + 8]);
                ah[mt][3] = *(const uint32_t*)(&Ah[r + 8][c + 8]);
                al[mt][0] = *(const uint32_t*)(&Al[r][c]);
                al[mt][1] = *(const uint32_t*)(&Al[r + 8][c]);
                al[mt][2] = *(const uint32_t*)(&Al[r][c + 8]);
                al[mt][3] = *(const uint32_t*)(&Al[r + 8][c + 8]);
            }
#pragma unroll
            for (int nt = 0; nt < 8; ++nt) {
                int n = wn * 64 + nt * 8 + (lane >> 2);
                int c = kk + (lane & 3) * 2;
                uint32_t bh[2], bl[2];
                bh[0] = *(const uint32_t*)(&Bh[n][c]);
                bh[1] = *(const uint32_t*)(&Bh[n][c + 8]);
                bl[0] = *(const uint32_t*)(&Bl[n][c]);
                bl[1] = *(const uint32_t*)(&Bl[n][c + 8]);
#pragma unroll
                for (int mt = 0; mt < 2; ++mt) {
                    mma16816(acc[mt][nt], ah[mt], bh);
                    mma16816(acc[mt][nt], ah[mt], bl);
                    mma16816(acc[mt][nt], al[mt], bh);
                }
            }
        }
        __syncthreads();
    }

#pragma unroll
    for (int mt = 0; mt < 2; ++mt)
#pragma unroll
        for (int nt = 0; nt < 8; ++nt) {
            int col = colBase + wn * 64 + nt * 8 + (lane & 3) * 2;
            if (col >= N) continue;
#pragma unroll
            for (int i = 0; i < 2; ++i) {
                int row = rowBase + wm * 32 + mt * 16 + (lane >> 2) + i * 8;
                if (row >= M) continue;
                float v0 = acc[mt][nt][i * 2 + 0] * scale;
                float v1 = acc[mt][nt][i * 2 + 1] * scale;
                if (bias) { v0 += bias[col]; v1 += bias[col + 1]; }
                long long o = cOff + (long long)row * ldc + col;
                if (residual) { v0 += residual[o]; v1 += residual[o + 1]; }
                C[o] = v0; C[o + 1] = v1;
            }
        }
}

// ---------------- host glue ----------------
static void gemm(const float* A, const float* W, const float* bias, const float* res,
                 float* C, int M, int N, int K, int Z,
                 long long aS, long long wS, long long cHi, long long cLo, int cDiv,
                 int ldc, float scale) {
    dim3 g((N + 127) / 128, (M + 127) / 128, Z);
    gemm_kernel<<<g, 256>>>(A, W, bias, res, C, M, N, K, aS, wS, cHi, cLo, cDiv, ldc, scale);
}

extern "C" void kernel_launch(void* const* d_in, const int* in_sizes, int n_in,
                              void* d_out, int out_size) {
    const float* x     = (const float*)d_in[0];
    const float* enc   = (const float*)d_in[1];
    const float* ln1g  = (const float*)d_in[2];
    const float* ln1b  = (const float*)d_in[3];
    const float* ln2g  = (const float*)d_in[4];
    const float* ln2b  = (const float*)d_in[5];
    const float* ln3g  = (const float*)d_in[6];
    const float* ln3b  = (const float*)d_in[7];
    const float* wq1   = (const float*)d_in[8];
    const float* wk1   = (const float*)d_in[9];
    const float* wv1   = (const float*)d_in[10];
    const float* wo1   = (const float*)d_in[11];
    const float* bo1   = (const float*)d_in[12];
    const float* wq2   = (const float*)d_in[13];
    const float* wk2   = (const float*)d_in[14];
    const float* wv2   = (const float*)d_in[15];
    const float* wo2   = (const float*)d_in[16];
    const float* bo2   = (const float*)d_in[17];
    const float* wgg   = (const float*)d_in[18];
    const float* bgg   = (const float*)d_in[19];
    const float* wff   = (const float*)d_in[20];
    const float* bff   = (const float*)d_in[21];
    float* out = (float*)d_out;

    float *h, *p1, *p2, *p3, *qh, *kh, *vT, *scores, *att, *xcur, *proj, *ff;
    cudaGetSymbolAddress((void**)&h,      g_h);
    cudaGetSymbolAddress((void**)&p1,     g_p1);
    cudaGetSymbolAddress((void**)&p2,     g_p2);
    cudaGetSymbolAddress((void**)&p3,     g_p3);
    cudaGetSymbolAddress((void**)&qh,     g_qh);
    cudaGetSymbolAddress((void**)&kh,     g_kh);
    cudaGetSymbolAddress((void**)&vT,     g_vT);
    cudaGetSymbolAddress((void**)&scores, g_scores);
    cudaGetSymbolAddress((void**)&att,    g_att);
    cudaGetSymbolAddress((void**)&xcur,   g_x);
    cudaGetSymbolAddress((void**)&proj,   g_proj);
    cudaGetSymbolAddress((void**)&ff,     g_ff);

    // ---- self attention ----
    ln_kernel<<<M1, 256>>>(x, ln1g, ln1b, h);
    gemm(h, wq1, nullptr, nullptr, p1, M1, HID, HID, 1, 0, 0, 0, 0, 1, HID, 1.f);
    gemm(h, wk1, nullptr, nullptr, p2, M1, HID, HID, 1, 0, 0, 0, 0, 1, HID, 1.f);
    gemm(h, wv1, nullptr, nullptr, p3, M1, HID, HID, 1, 0, 0, 0, 0, 1, HID, 1.f);
    {
        long long nq = (long long)NBH * TQ * HD;
        reshape_q_kernel<<<(unsigned)((nq + 255) / 256), 256>>>(p1, qh);
        reshape_k_kernel<<<(unsigned)((nq + 255) / 256), 256>>>(p2, kh, TQ, TQ);
        reshape_vT_kernel<<<(unsigned)((nq + 255) / 256), 256>>>(p3, vT, TQ, TQ);
    }
    gemm(qh, kh, nullptr, nullptr, scores, TQ, TQ, HD, NBH,
         (long long)TQ * HD, (long long)TQ * HD, (long long)TQ * TQ, 0, 1, TQ, 0.125f);
    softmax_kernel<<<NBH * TQ, 256>>>(scores, TQ, TQ);
    gemm(scores, vT, nullptr, nullptr, att, TQ, HD, TQ, NBH,
         (long long)TQ * TQ, (long long)HD * TQ,
         (long long)TQ * HID, (long long)HD, NH, HID, 1.f);
    gemm(att, wo1, bo1, x, xcur, M1, HID, HID, 1, 0, 0, 0, 0, 1, HID, 1.f);

    // ---- cross attention ----
    ln_kernel<<<M1, 256>>>(xcur, ln2g, ln2b, h);
    gemm(h, wq2, nullptr, nullptr, p1, M1, HID, HID, 1, 0, 0, 0, 0, 1, HID, 1.f);
    gemm(enc, wk2, nullptr, nullptr, p2, MENC, HID, CROSSD, 1, 0, 0, 0, 0, 1, HID, 1.f);
    gemm(enc, wv2, nullptr, nullptr, p3, MENC, HID, CROSSD, 1, 0, 0, 0, 0, 1, HID, 1.f);
    {
        long long nq = (long long)NBH * TQ * HD;
        long long nk = (long long)NBH * SPAD * HD;
        reshape_q_kernel<<<(unsigned)((nq + 255) / 256), 256>>>(p1, qh);
        reshape_k_kernel<<<(unsigned)((nk + 255) / 256), 256>>>(p2, kh, SENC, SPAD);
        reshape_vT_kernel<<<(unsigned)((nk + 255) / 256), 256>>>(p3, vT, SENC, SPAD);
    }
    gemm(qh, kh, nullptr, nullptr, scores, TQ, SPAD, HD, NBH,
         (long long)TQ * HD, (long long)SPAD * HD, (long long)TQ * SPAD, 0, 1, SPAD, 0.125f);
    softmax_kernel<<<NBH * TQ, 256>>>(scores, SPAD, SENC);
    gemm(scores, vT, nullptr, nullptr, att, TQ, HD, SPAD, NBH,
         (long long)TQ * SPAD, (long long)HD * SPAD,
         (long long)TQ * HID, (long long)HD, NH, HID, 1.f);
    gemm(att, wo2, bo2, xcur, xcur, M1, HID, HID, 1, 0, 0, 0, 0, 1, HID, 1.f);

    // ---- GEGLU FF ----
    ln_kernel<<<M1, 256>>>(xcur, ln3g, ln3b, h);
    gemm(h, wgg, bgg, nullptr, proj, M1, 2 * FFD, HID, 1, 0, 0, 0, 0, 1, 2 * FFD, 1.f);
    {
        long long n = (long long)M1 * FFD;
        geglu_kernel<<<(unsigned)((n + 255) / 256), 256>>>(proj, ff);
    }
    gemm(ff, wff, bff, xcur, out, M1, HID, FFD, 1, 0, 0, 0, 0, 1, HID, 1.f);

    (void)in_sizes; (void)n_in; (void)out_size;
}

// round 5
// speedup vs baseline: 1.7850x; 1.7850x over previous
#include <cuda_runtime.h>
#include <cuda_bf16.h>
#include <cstdint>

typedef __nv_bfloat16 bf16;

#define BATCH 2
#define TQ    2048
#define HID   1280
#define NH    20
#define HD    64
#define CROSSD 2048
#define SENC  77
#define SPAD  128
#define FFD   5120
#define M1    (BATCH*TQ)     /* 4096 */
#define MENC  (BATCH*SENC)   /* 154  */
#define NBH   (BATCH*NH)     /* 40   */

// ---------------- scratch (device globals; no allocation) ----------------
__device__ float g_h   [M1*HID];
__device__ float g_p1  [M1*HID];
__device__ float g_p2  [M1*HID];
__device__ float g_p3  [M1*HID];
__device__ float g_qh  [(size_t)NBH*TQ*HD];
__device__ float g_kh  [(size_t)NBH*TQ*HD];
__device__ float g_vT  [(size_t)NBH*HD*TQ];
__device__ float g_scores[(size_t)NBH*TQ*TQ];   // fp32, softmax in-place
__device__ float g_att [M1*HID];
__device__ float g_x   [M1*HID];
__device__ float g_proj[(size_t)M1*2*FFD];
__device__ float g_ff  [(size_t)M1*FFD];

// ---------------- elementwise kernels ----------------
__global__ void ln_kernel(const float* __restrict__ x, const float* __restrict__ g,
                          const float* __restrict__ b, float* __restrict__ out) {
    __shared__ float red[256];
    int row = blockIdx.x, tid = threadIdx.x;
    const float* xr = x + (long long)row * HID;
    float v[5], s = 0.f;
#pragma unroll
    for (int i = 0; i < 5; i++) { v[i] = xr[tid + i * 256]; s += v[i]; }
    red[tid] = s; __syncthreads();
    for (int o = 128; o > 0; o >>= 1) { if (tid < o) red[tid] += red[tid + o]; __syncthreads(); }
    float mu = red[0] * (1.0f / HID);
    __syncthreads();
    float sq = 0.f;
#pragma unroll
    for (int i = 0; i < 5; i++) { float d = v[i] - mu; sq += d * d; }
    red[tid] = sq; __syncthreads();
    for (int o = 128; o > 0; o >>= 1) { if (tid < o) red[tid] += red[tid + o]; __syncthreads(); }
    float rs = rsqrtf(red[0] * (1.0f / HID) + 1e-5f);
#pragma unroll
    for (int i = 0; i < 5; i++) {
        int c = tid + i * 256;
        out[(long long)row * HID + c] = (v[i] - mu) * rs * g[c] + b[c];
    }
}

__global__ void reshape_q_kernel(const float* __restrict__ q, float* __restrict__ qh) {
    long long idx = (long long)blockIdx.x * blockDim.x + threadIdx.x;
    if (idx >= (long long)NBH * TQ * HD) return;
    int d = idx & (HD - 1);
    long long r = idx >> 6;
    int t = (int)(r % TQ);
    long long bh = r / TQ;
    int h = (int)(bh % NH), b = (int)(bh / NH);
    qh[idx] = q[((long long)(b * TQ + t)) * HID + h * HD + d];
}

__global__ void reshape_k_kernel(const float* __restrict__ k, float* __restrict__ kh, int S, int Spad) {
    long long idx = (long long)blockIdx.x * blockDim.x + threadIdx.x;
    long long tot = (long long)NBH * Spad * HD;
    if (idx >= tot) return;
    int d = idx & (HD - 1);
    long long r = idx >> 6;
    int s = (int)(r % Spad);
    long long bh = r / Spad;
    int h = (int)(bh % NH), b = (int)(bh / NH);
    float val = 0.f;
    if (s < S) val = k[((long long)(b * S + s)) * HID + h * HD + d];
    kh[idx] = val;
}

__global__ void reshape_vT_kernel(const float* __restrict__ v, float* __restrict__ vT, int S, int Spad) {
    long long idx = (long long)blockIdx.x * blockDim.x + threadIdx.x;
    long long tot = (long long)NBH * HD * Spad;
    if (idx >= tot) return;
    int s = (int)(idx % Spad);
    long long r = idx / Spad;
    int d = (int)(r % HD);
    long long bh = r / HD;
    int h = (int)(bh % NH), b = (int)(bh / NH);
    float val = 0.f;
    if (s < S) val = v[((long long)(b * S + s)) * HID + h * HD + d];
    vT[idx] = val;
}

__global__ void softmax_kernel(float* __restrict__ S, int Spad, int Sval) {
    __shared__ float red[256];
    long long row = blockIdx.x;
    float* sr = S + row * (long long)Spad;
    int tid = threadIdx.x;
    float vals[8];
    int cnt = 0;
    float mx = -1e30f;
    for (int j = tid; j < Sval; j += 256) { float v = sr[j]; vals[cnt++] = v; mx = fmaxf(mx, v); }
    red[tid] = mx; __syncthreads();
    for (int o = 128; o > 0; o >>= 1) { if (tid < o) red[tid] = fmaxf(red[tid], red[tid + o]); __syncthreads(); }
    mx = red[0]; __syncthreads();
    float sum = 0.f;
    for (int i = 0; i < cnt; i++) { vals[i] = expf(vals[i] - mx); sum += vals[i]; }
    red[tid] = sum; __syncthreads();
    for (int o = 128; o > 0; o >>= 1) { if (tid < o) red[tid] += red[tid + o]; __syncthreads(); }
    float inv = 1.f / red[0];
    cnt = 0;
    for (int j = tid; j < Spad; j += 256) {
        float o = (j < Sval) ? vals[cnt++] * inv : 0.f;
        sr[j] = o;
    }
}

__global__ void geglu_kernel(const float* __restrict__ proj, float* __restrict__ out) {
    long long i = (long long)blockIdx.x * blockDim.x + threadIdx.x;
    if (i >= (long long)M1 * FFD) return;
    long long r = i / FFD;
    int c = (int)(i % FFD);
    float x1 = proj[r * (2 * FFD) + c];
    float x2 = proj[r * (2 * FFD) + FFD + c];
    float gel = 0.5f * x2 * (1.0f + erff(x2 * 0.7071067811865476f));
    out[i] = x1 * gel;
}

// ---------------- pipelined batched split-bf16 tensor-core GEMM ----------------
// C[z][M][N] = scale * (A[z] @ W[z]^T) + bias + residual   (fp32 in/out)
// A = Ah + Al, W = Wh + Wl (bf16 hi/lo); product = Ah*Wh + Ah*Wl + Al*Wh in fp32.
// 2-stage double-buffered smem, 1 __syncthreads per k-tile, LDG prefetch in regs.
__device__ __forceinline__ void mma16816(float c[4], const uint32_t a[4], const uint32_t b[2]) {
    asm volatile(
        "mma.sync.aligned.m16n8k16.row.col.f32.bf16.bf16.f32 "
        "{%0,%1,%2,%3}, {%4,%5,%6,%7}, {%8,%9}, {%0,%1,%2,%3};\n"
        : "+f"(c[0]), "+f"(c[1]), "+f"(c[2]), "+f"(c[3])
        : "r"(a[0]), "r"(a[1]), "r"(a[2]), "r"(a[3]), "r"(b[0]), "r"(b[1]));
}

#define TILE_ELE (128 * 40)
#define SMEM_BYTES (8 * TILE_ELE * 2)   /* 81920 */

__global__ __launch_bounds__(256) void gemm_kernel(
    const float* __restrict__ A, const float* __restrict__ W,
    const float* __restrict__ bias, const float* __restrict__ residual,
    float* __restrict__ C,
    int M, int N, int K,
    long long aStride, long long wStride,
    long long cHi, long long cLo, int cDiv, int ldc, float scale)
{
    extern __shared__ __align__(16) bf16 sm[];
    bf16* sAh = sm;                 // [2][128][40]
    bf16* sAl = sm + 2 * TILE_ELE;
    bf16* sBh = sm + 4 * TILE_ELE;
    bf16* sBl = sm + 6 * TILE_ELE;

    int z = blockIdx.z;
    A += (long long)z * aStride;
    W += (long long)z * wStride;
    long long cOff = (long long)(z / cDiv) * cHi + (long long)(z % cDiv) * cLo;

    int tid = threadIdx.x;
    int lane = tid & 31, warp = tid >> 5;
    int wm = warp >> 1, wn = warp & 1;
    int rowBase = blockIdx.y * 128;
    int colBase = blockIdx.x * 128;

    // load mapping: thread covers 4 float4 per operand per tile
    int lr[4], lc[4];
#pragma unroll
    for (int it = 0; it < 4; ++it) {
        int i = tid + it * 256;
        lr[it] = i >> 3;
        lc[it] = (i & 7) << 2;
    }

    float acc[2][8][4];
#pragma unroll
    for (int i = 0; i < 2; i++)
#pragma unroll
        for (int j = 0; j < 8; j++)
#pragma unroll
            for (int l = 0; l < 4; l++) acc[i][j][l] = 0.f;

    float4 pa[4], pb[4];

    int kTiles = K >> 5;

    // prefetch tile 0
#pragma unroll
    for (int it = 0; it < 4; ++it) {
        int gr = rowBase + lr[it];
        pa[it] = (gr < M) ? *(const float4*)(A + (long long)gr * K + lc[it])
                          : make_float4(0.f, 0.f, 0.f, 0.f);
        int gn = colBase + lr[it];
        pb[it] = (gn < N) ? *(const float4*)(W + (long long)gn * K + lc[it])
                          : make_float4(0.f, 0.f, 0.f, 0.f);
    }

    for (int kt = 0; kt < kTiles; ++kt) {
        int s = kt & 1;
        // store prefetched regs -> smem stage s (hi/lo split, packed 32-bit stores)
        {
            bf16* Ah = sAh + s * TILE_ELE;
            bf16* Al = sAl + s * TILE_ELE;
            bf16* Bh = sBh + s * TILE_ELE;
            bf16* Bl = sBl + s * TILE_ELE;
#pragma unroll
            for (int it = 0; it < 4; ++it) {
                int off = lr[it] * 40 + lc[it];
                float4 va = pa[it];
                __nv_bfloat162 h0 = __floats2bfloat162_rn(va.x, va.y);
                __nv_bfloat162 h1 = __floats2bfloat162_rn(va.z, va.w);
                __nv_bfloat162 l0 = __floats2bfloat162_rn(va.x - __bfloat162float(h0.x),
                                                          va.y - __bfloat162float(h0.y));
                __nv_bfloat162 l1 = __floats2bfloat162_rn(va.z - __bfloat162float(h1.x),
                                                          va.w - __bfloat162float(h1.y));
                *(__nv_bfloat162*)(Ah + off)     = h0;
                *(__nv_bfloat162*)(Ah + off + 2) = h1;
                *(__nv_bfloat162*)(Al + off)     = l0;
                *(__nv_bfloat162*)(Al + off + 2) = l1;
                float4 vb = pb[it];
                h0 = __floats2bfloat162_rn(vb.x, vb.y);
                h1 = __floats2bfloat162_rn(vb.z, vb.w);
                l0 = __floats2bfloat162_rn(vb.x - __bfloat162float(h0.x),
                                           vb.y - __bfloat162float(h0.y));
                l1 = __floats2bfloat162_rn(vb.z - __bfloat162float(h1.x),
                                           vb.w - __bfloat162float(h1.y));
                *(__nv_bfloat162*)(Bh + off)     = h0;
                *(__nv_bfloat162*)(Bh + off + 2) = h1;
                *(__nv_bfloat162*)(Bl + off)     = l0;
                *(__nv_bfloat162*)(Bl + off + 2) = l1;
            }
        }
        __syncthreads();

        // prefetch next tile into regs (LDG latency overlapped with compute)
        if (kt + 1 < kTiles) {
            int k0 = (kt + 1) << 5;
#pragma unroll
            for (int it = 0; it < 4; ++it) {
                int gr = rowBase + lr[it];
                pa[it] = (gr < M) ? *(const float4*)(A + (long long)gr * K + k0 + lc[it])
                                  : make_float4(0.f, 0.f, 0.f, 0.f);
                int gn = colBase + lr[it];
                pb[it] = (gn < N) ? *(const float4*)(W + (long long)gn * K + k0 + lc[it])
                                  : make_float4(0.f, 0.f, 0.f, 0.f);
            }
        }

        // compute on stage s
        const bf16* Ah = sAh + s * TILE_ELE;
        const bf16* Al = sAl + s * TILE_ELE;
        const bf16* Bh = sBh + s * TILE_ELE;
        const bf16* Bl = sBl + s * TILE_ELE;
#pragma unroll
        for (int kk = 0; kk < 32; kk += 16) {
            uint32_t ah[2][4], al[2][4];
#pragma unroll
            for (int mt = 0; mt < 2; ++mt) {
                int r = wm * 32 + mt * 16 + (lane >> 2);
                int c = kk + (lane & 3) * 2;
                ah[mt][0] = *(const uint32_t*)(Ah + r * 40 + c);
                ah[mt][1] = *(const uint32_t*)(Ah + (r + 8) * 40 + c);
                ah[mt][2] = *(const uint32_t*)(Ah + r * 40 + c + 8);
                ah[mt][3] = *(const uint32_t*)(Ah + (r + 8) * 40 + c + 8);
                al[mt][0] = *(const uint32_t*)(Al + r * 40 + c);
                al[mt][1] = *(const uint32_t*)(Al + (r + 8) * 40 + c);
                al[mt][2] = *(const uint32_t*)(Al + r * 40 + c + 8);
                al[mt][3] = *(const uint32_t*)(Al + (r + 8) * 40 + c + 8);
            }
#pragma unroll
            for (int nt = 0; nt < 8; ++nt) {
                int n = wn * 64 + nt * 8 + (lane >> 2);
                int c = kk + (lane & 3) * 2;
                uint32_t bh[2], bl[2];
                bh[0] = *(const uint32_t*)(Bh + n * 40 + c);
                bh[1] = *(const uint32_t*)(Bh + n * 40 + c + 8);
                bl[0] = *(const uint32_t*)(Bl + n * 40 + c);
                bl[1] = *(const uint32_t*)(Bl + n * 40 + c + 8);
#pragma unroll
                for (int mt = 0; mt < 2; ++mt) {
                    mma16816(acc[mt][nt], ah[mt], bh);
                    mma16816(acc[mt][nt], ah[mt], bl);
                    mma16816(acc[mt][nt], al[mt], bh);
                }
            }
        }
    }

#pragma unroll
    for (int mt = 0; mt < 2; ++mt)
#pragma unroll
        for (int nt = 0; nt < 8; ++nt) {
            int col = colBase + wn * 64 + nt * 8 + (lane & 3) * 2;
            if (col >= N) continue;
#pragma unroll
            for (int i = 0; i < 2; ++i) {
                int row = rowBase + wm * 32 + mt * 16 + (lane >> 2) + i * 8;
                if (row >= M) continue;
                float v0 = acc[mt][nt][i * 2 + 0] * scale;
                float v1 = acc[mt][nt][i * 2 + 1] * scale;
                if (bias) { v0 += bias[col]; v1 += bias[col + 1]; }
                long long o = cOff + (long long)row * ldc + col;
                if (residual) { v0 += residual[o]; v1 += residual[o + 1]; }
                C[o] = v0; C[o + 1] = v1;
            }
        }
}

// ---------------- host glue ----------------
static void gemm(const float* A, const float* W, const float* bias, const float* res,
                 float* C, int M, int N, int K, int Z,
                 long long aS, long long wS, long long cHi, long long cLo, int cDiv,
                 int ldc, float scale) {
    dim3 g((N + 127) / 128, (M + 127) / 128, Z);
    gemm_kernel<<<g, 256, SMEM_BYTES>>>(A, W, bias, res, C, M, N, K, aS, wS, cHi, cLo, cDiv, ldc, scale);
}

extern "C" void kernel_launch(void* const* d_in, const int* in_sizes, int n_in,
                              void* d_out, int out_size) {
    const float* x     = (const float*)d_in[0];
    const float* enc   = (const float*)d_in[1];
    const float* ln1g  = (const float*)d_in[2];
    const float* ln1b  = (const float*)d_in[3];
    const float* ln2g  = (const float*)d_in[4];
    const float* ln2b  = (const float*)d_in[5];
    const float* ln3g  = (const float*)d_in[6];
    const float* ln3b  = (const float*)d_in[7];
    const float* wq1   = (const float*)d_in[8];
    const float* wk1   = (const float*)d_in[9];
    const float* wv1   = (const float*)d_in[10];
    const float* wo1   = (const float*)d_in[11];
    const float* bo1   = (const float*)d_in[12];
    const float* wq2   = (const float*)d_in[13];
    const float* wk2   = (const float*)d_in[14];
    const float* wv2   = (const float*)d_in[15];
    const float* wo2   = (const float*)d_in[16];
    const float* bo2   = (const float*)d_in[17];
    const float* wgg   = (const float*)d_in[18];
    const float* bgg   = (const float*)d_in[19];
    const float* wff   = (const float*)d_in[20];
    const float* bff   = (const float*)d_in[21];
    float* out = (float*)d_out;

    static bool attr_done = false;
    if (!attr_done) {
        cudaFuncSetAttribute(gemm_kernel, cudaFuncAttributeMaxDynamicSharedMemorySize, SMEM_BYTES);
        attr_done = true;
    }

    float *h, *p1, *p2, *p3, *qh, *kh, *vT, *scores, *att, *xcur, *proj, *ff;
    cudaGetSymbolAddress((void**)&h,      g_h);
    cudaGetSymbolAddress((void**)&p1,     g_p1);
    cudaGetSymbolAddress((void**)&p2,     g_p2);
    cudaGetSymbolAddress((void**)&p3,     g_p3);
    cudaGetSymbolAddress((void**)&qh,     g_qh);
    cudaGetSymbolAddress((void**)&kh,     g_kh);
    cudaGetSymbolAddress((void**)&vT,     g_vT);
    cudaGetSymbolAddress((void**)&scores, g_scores);
    cudaGetSymbolAddress((void**)&att,    g_att);
    cudaGetSymbolAddress((void**)&xcur,   g_x);
    cudaGetSymbolAddress((void**)&proj,   g_proj);
    cudaGetSymbolAddress((void**)&ff,     g_ff);

    // ---- self attention ----
    ln_kernel<<<M1, 256>>>(x, ln1g, ln1b, h);
    gemm(h, wq1, nullptr, nullptr, p1, M1, HID, HID, 1, 0, 0, 0, 0, 1, HID, 1.f);
    gemm(h, wk1, nullptr, nullptr, p2, M1, HID, HID, 1, 0, 0, 0, 0, 1, HID, 1.f);
    gemm(h, wv1, nullptr, nullptr, p3, M1, HID, HID, 1, 0, 0, 0, 0, 1, HID, 1.f);
    {
        long long nq = (long long)NBH * TQ * HD;
        reshape_q_kernel<<<(unsigned)((nq + 255) / 256), 256>>>(p1, qh);
        reshape_k_kernel<<<(unsigned)((nq + 255) / 256), 256>>>(p2, kh, TQ, TQ);
        reshape_vT_kernel<<<(unsigned)((nq + 255) / 256), 256>>>(p3, vT, TQ, TQ);
    }
    gemm(qh, kh, nullptr, nullptr, scores, TQ, TQ, HD, NBH,
         (long long)TQ * HD, (long long)TQ * HD, (long long)TQ * TQ, 0, 1, TQ, 0.125f);
    softmax_kernel<<<NBH * TQ, 256>>>(scores, TQ, TQ);
    gemm(scores, vT, nullptr, nullptr, att, TQ, HD, TQ, NBH,
         (long long)TQ * TQ, (long long)HD * TQ,
         (long long)TQ * HID, (long long)HD, NH, HID, 1.f);
    gemm(att, wo1, bo1, x, xcur, M1, HID, HID, 1, 0, 0, 0, 0, 1, HID, 1.f);

    // ---- cross attention ----
    ln_kernel<<<M1, 256>>>(xcur, ln2g, ln2b, h);
    gemm(h, wq2, nullptr, nullptr, p1, M1, HID, HID, 1, 0, 0, 0, 0, 1, HID, 1.f);
    gemm(enc, wk2, nullptr, nullptr, p2, MENC, HID, CROSSD, 1, 0, 0, 0, 0, 1, HID, 1.f);
    gemm(enc, wv2, nullptr, nullptr, p3, MENC, HID, CROSSD, 1, 0, 0, 0, 0, 1, HID, 1.f);
    {
        long long nq = (long long)NBH * TQ * HD;
        long long nk = (long long)NBH * SPAD * HD;
        reshape_q_kernel<<<(unsigned)((nq + 255) / 256), 256>>>(p1, qh);
        reshape_k_kernel<<<(unsigned)((nk + 255) / 256), 256>>>(p2, kh, SENC, SPAD);
        reshape_vT_kernel<<<(unsigned)((nk + 255) / 256), 256>>>(p3, vT, SENC, SPAD);
    }
    gemm(qh, kh, nullptr, nullptr, scores, TQ, SPAD, HD, NBH,
         (long long)TQ * HD, (long long)SPAD * HD, (long long)TQ * SPAD, 0, 1, SPAD, 0.125f);
    softmax_kernel<<<NBH * TQ, 256>>>(scores, SPAD, SENC);
    gemm(scores, vT, nullptr, nullptr, att, TQ, HD, SPAD, NBH,
         (long long)TQ * SPAD, (long long)HD * SPAD,
         (long long)TQ * HID, (long long)HD, NH, HID, 1.f);
    gemm(att, wo2, bo2, xcur, xcur, M1, HID, HID, 1, 0, 0, 0, 0, 1, HID, 1.f);

    // ---- GEGLU FF ----
    ln_kernel<<<M1, 256>>>(xcur, ln3g, ln3b, h);
    gemm(h, wgg, bgg, nullptr, proj, M1, 2 * FFD, HID, 1, 0, 0, 0, 0, 1, 2 * FFD, 1.f);
    {
        long long n = (long long)M1 * FFD;
        geglu_kernel<<<(unsigned)((n + 255) / 256), 256>>>(proj, ff);
    }
    gemm(ff, wff, bff, xcur, out, M1, HID, FFD, 1, 0, 0, 0, 0, 1, HID, 1.f);

    (void)in_sizes; (void)n_in; (void)out_size;
}